// round 2
// baseline (speedup 1.0000x reference)
#include <cuda_runtime.h>

// ============================================================================
// SNN ResNet forward, 8 timesteps. fp32 implicit-GEMM convs with fused LIF.
// ============================================================================

#define BATCH 32
#define KC 16
#define TIMESTEPS 8

// Membrane arena (zeroed each launch) + activation ping-pong buffers.
__device__ float g_mem[8257536];
__device__ float g_bufA[2097152];
__device__ float g_bufB[2097152];
__device__ float g_bufC[2097152];

struct ConvP {
    const float* in;
    const float* w;
    float*       out;
    float*       mem;      // membrane (LIF mode)
    const float* res;      // residual added to conv delta (or null)
    const float* mask;     // dropout mask multiplied into spike (or null)
    const float* thr;
    const float* leak;
    int li;                // layer index into thr/leak
    int Cin, Hin, Win;
    int Cout, Hout, Wout;
    int KH;                // 3 or 1
    int stride, pad;
    int mode;              // 0 = raw store (shortcut conv), 1 = LIF epilogue
};

// Implicit GEMM: out[Cout x (B*Ho*Wo)], K = Cin*KH*KH.
// 64x64 tile, 256 threads, 4x4 per-thread register block, KC-deep smem chunks.
__global__ __launch_bounds__(256) void conv_gemm_lif(ConvP p) {
    __shared__ __align__(16) float As[KC][64];  // [k][co]
    __shared__ __align__(16) float Bs[KC][64];  // [k][pos]

    const int tid = threadIdx.x;
    const int tx = tid & 15;       // position sub-tile
    const int ty = tid >> 4;       // channel sub-tile
    const int pos0 = blockIdx.x * 64;
    const int co0  = blockIdx.y * 64;
    const int HW = p.Hout * p.Wout;
    const int KK = p.KH * p.KH;
    const int K  = p.Cin * KK;

    // ---- A loader mapping: thread covers (lm, k = lkq*4 .. lkq*4+3) ----
    const int lm  = tid >> 2;      // 0..63 : co within tile
    const int lkq = tid & 3;       // 0..3
    const float* wrow = p.w + (size_t)(co0 + lm) * K;

    // ---- B loader mapping: thread covers (lp, k = lbq*4 .. lbq*4+3) ----
    const int lp  = tid & 63;      // 0..63 : pos within tile
    const int lbq = tid >> 6;      // 0..3
    const int pp  = pos0 + lp;
    const int pb  = pp / HW;
    const int phw = pp - pb * HW;
    const int py  = phw / p.Wout;
    const int px  = phw - py * p.Wout;
    const int iy0 = py * p.stride - p.pad;
    const int ix0 = px * p.stride - p.pad;
    const float* inb = p.in + (size_t)pb * p.Cin * p.Hin * p.Win;

    float acc[4][4];
#pragma unroll
    for (int i = 0; i < 4; i++)
#pragma unroll
        for (int j = 0; j < 4; j++) acc[i][j] = 0.f;

    for (int k0 = 0; k0 < K; k0 += KC) {
        // stage A (weights): coalesced along k within each co row
#pragma unroll
        for (int i = 0; i < 4; i++) {
            int k  = lkq * 4 + i;
            int kk = k0 + k;
            As[k][lm] = (kk < K) ? wrow[kk] : 0.f;
        }
        // stage B (im2col gather): coalesced along pos for each k
#pragma unroll
        for (int i = 0; i < 4; i++) {
            int k  = lbq * 4 + i;
            int kk = k0 + k;
            float v = 0.f;
            if (kk < K) {
                int ci = kk / KK;
                int r  = kk - ci * KK;
                int ky = r / p.KH;
                int kx = r - ky * p.KH;
                int iy = iy0 + ky;
                int ix = ix0 + kx;
                if (iy >= 0 && iy < p.Hin && ix >= 0 && ix < p.Win)
                    v = inb[((size_t)ci * p.Hin + iy) * p.Win + ix];
            }
            Bs[k][lp] = v;
        }
        __syncthreads();

#pragma unroll
        for (int k = 0; k < KC; k++) {
            float4 a  = *(const float4*)&As[k][ty * 4];
            float4 bv = *(const float4*)&Bs[k][tx * 4];
            acc[0][0] += a.x * bv.x; acc[0][1] += a.x * bv.y;
            acc[0][2] += a.x * bv.z; acc[0][3] += a.x * bv.w;
            acc[1][0] += a.y * bv.x; acc[1][1] += a.y * bv.y;
            acc[1][2] += a.y * bv.z; acc[1][3] += a.y * bv.w;
            acc[2][0] += a.z * bv.x; acc[2][1] += a.z * bv.y;
            acc[2][2] += a.z * bv.z; acc[2][3] += a.z * bv.w;
            acc[3][0] += a.w * bv.x; acc[3][1] += a.w * bv.y;
            acc[3][2] += a.w * bv.z; acc[3][3] += a.w * bv.w;
        }
        __syncthreads();
    }

    // ---- epilogue: raw store or fused LIF ----
    float th = 1.f, lkf = 1.f;
    if (p.mode == 1) { th = p.thr[p.li]; lkf = p.leak[p.li]; }

#pragma unroll
    for (int j = 0; j < 4; j++) {
        int pj = pos0 + tx * 4 + j;
        int b  = pj / HW;
        int hw = pj - b * HW;
        size_t base = ((size_t)b * p.Cout + co0 + ty * 4) * HW + hw;
#pragma unroll
        for (int i = 0; i < 4; i++) {
            size_t g = base + (size_t)i * HW;
            float d = acc[i][j];
            if (p.mode == 0) {
                p.out[g] = d;
            } else {
                if (p.res) d += p.res[g];
                float m  = lkf * p.mem[g] + d;      // leaky integrate
                float mt = m / th - 1.f;            // normalized membrane
                float s  = (mt > 0.f) ? 1.f : 0.f;  // spike
                p.mem[g] = m - th * s;              // soft reset
                float o  = s;
                if (p.mask) o *= p.mask[g];
                p.out[g] = o;
            }
        }
    }
}

__global__ void zero_kernel(float* mem, int n, float* out, int nout) {
    int i = blockIdx.x * blockDim.x + threadIdx.x;
    if (i < n) mem[i] = 0.f;
    if (i < nout) out[i] = 0.f;
}

__global__ void avgpool2_kernel(const float* in, float* out, int C, int H, int W) {
    int Ho = H >> 1, Wo = W >> 1;
    int total = BATCH * C * Ho * Wo;
    int idx = blockIdx.x * blockDim.x + threadIdx.x;
    if (idx >= total) return;
    int x = idx % Wo; int t = idx / Wo;
    int y = t % Ho;   t /= Ho;
    int c = t % C;    int b = t / C;
    const float* pptr = in + (((size_t)b * C + c) * H + y * 2) * W + x * 2;
    out[idx] = 0.25f * (pptr[0] + pptr[1] + pptr[W] + pptr[W + 1]);
}

// mfc[b,k] += dot(o[b,:], wfc[k,:]) ; one block per (b,k)
__global__ void fc_acc_kernel(const float* o, const float* wfc, float* out) {
    int bk = blockIdx.x;
    int b = bk / 10, k = bk % 10;
    const float* op = o + (size_t)b * 2048;
    const float* wp = wfc + (size_t)k * 2048;
    float s = 0.f;
    for (int j = threadIdx.x; j < 2048; j += 128) s += op[j] * wp[j];
    __shared__ float red[128];
    red[threadIdx.x] = s;
    __syncthreads();
    for (int st = 64; st > 0; st >>= 1) {
        if (threadIdx.x < st) red[threadIdx.x] += red[threadIdx.x + st];
        __syncthreads();
    }
    if (threadIdx.x == 0) out[b * 10 + k] += red[0];
}

// ============================================================================
// Host side
// ============================================================================

static void launch_conv(const float* in, const float* w, float* out,
                        float* mem, const float* res, const float* mask,
                        const float* thr, const float* leak, int li,
                        int Cin, int Hin, int Win,
                        int Cout, int Hout, int Wout,
                        int KH, int stride, int pad, int mode) {
    ConvP p;
    p.in = in; p.w = w; p.out = out; p.mem = mem; p.res = res; p.mask = mask;
    p.thr = thr; p.leak = leak; p.li = li;
    p.Cin = Cin; p.Hin = Hin; p.Win = Win;
    p.Cout = Cout; p.Hout = Hout; p.Wout = Wout;
    p.KH = KH; p.stride = stride; p.pad = pad; p.mode = mode;
    int N = BATCH * Hout * Wout;
    dim3 grid(N / 64, Cout / 64);
    conv_gemm_lif<<<grid, 256>>>(p);
}

extern "C" void kernel_launch(void* const* d_in, const int* in_sizes, int n_in,
                              void* d_out, int out_size) {
    const float* x      = (const float*)d_in[0];
    const float* w_pre0 = (const float*)d_in[1];
    const float* w_pre1 = (const float*)d_in[2];
    const float* w_pre2 = (const float*)d_in[3];
    const float* w1a    = (const float*)d_in[4];
    const float* w1b    = (const float*)d_in[5];
    const float* w2a    = (const float*)d_in[6];
    const float* w2b    = (const float*)d_in[7];
    const float* w2i    = (const float*)d_in[8];
    const float* w3a    = (const float*)d_in[9];
    const float* w3b    = (const float*)d_in[10];
    const float* w3i    = (const float*)d_in[11];
    const float* w4a    = (const float*)d_in[12];
    const float* w4b    = (const float*)d_in[13];
    const float* w4i    = (const float*)d_in[14];
    const float* w_fc   = (const float*)d_in[15];
    const float* thr    = (const float*)d_in[16];
    const float* leak   = (const float*)d_in[17];
    const float* mask2  = (const float*)d_in[18];
    const float* mask5  = (const float*)d_in[19];
    const float* mask9  = (const float*)d_in[20];
    const float* mask11 = (const float*)d_in[21];
    const float* mask13 = (const float*)d_in[22];
    const float* mask15 = (const float*)d_in[23];

    float *memBase, *bufA, *bufB, *bufC;
    cudaGetSymbolAddress((void**)&memBase, g_mem);
    cudaGetSymbolAddress((void**)&bufA, g_bufA);
    cudaGetSymbolAddress((void**)&bufB, g_bufB);
    cudaGetSymbolAddress((void**)&bufC, g_bufC);
    float* out = (float*)d_out;

    // membrane offsets
    float* m0  = memBase + 0;
    float* m1  = memBase + 2097152;
    float* m2  = memBase + 4194304;
    float* m3  = memBase + 6291456;
    float* m4  = memBase + 6815744;
    float* m5  = memBase + 7340032;
    float* m6  = memBase + 7602176;
    float* m7  = memBase + 7864320;
    float* m8  = memBase + 7995392;
    float* m9  = memBase + 8126464;
    float* m10 = memBase + 8192000;

    zero_kernel<<<(8257536 + 255) / 256, 256>>>(memBase, 8257536, out, 320);

    for (int t = 0; t < TIMESTEPS; t++) {
        // pre_process
        launch_conv(x,    w_pre0, bufA, m0, nullptr, mask2, thr, leak, 0, 3, 32, 32, 64, 32, 32, 3, 1, 1, 1);
        launch_conv(bufA, w_pre1, bufB, m1, nullptr, mask5, thr, leak, 1, 64, 32, 32, 64, 32, 32, 3, 1, 1, 1);
        launch_conv(bufB, w_pre2, bufA, m2, nullptr, nullptr, thr, leak, 2, 64, 32, 32, 64, 32, 32, 3, 1, 1, 1);
        avgpool2_kernel<<<(BATCH * 64 * 16 * 16 + 255) / 256, 256>>>(bufA, bufB, 64, 32, 32);
        // layer1 (identity shortcut) : inp = bufB
        launch_conv(bufB, w1a, bufA, m3, nullptr, mask9, thr, leak, 3, 64, 16, 16, 64, 16, 16, 3, 1, 1, 1);
        launch_conv(bufA, w1b, bufC, m4, bufB, nullptr, thr, leak, 4, 64, 16, 16, 64, 16, 16, 3, 1, 1, 1);
        // layer2 : inp = bufC
        launch_conv(bufC, w2a, bufA, m5, nullptr, mask11, thr, leak, 5, 64, 16, 16, 128, 8, 8, 3, 2, 1, 1);
        launch_conv(bufC, w2i, bufB, nullptr, nullptr, nullptr, thr, leak, 0, 64, 16, 16, 128, 8, 8, 1, 2, 0, 0);
        launch_conv(bufA, w2b, bufC, m6, bufB, nullptr, thr, leak, 6, 128, 8, 8, 128, 8, 8, 3, 1, 1, 1);
        // layer3 : inp = bufC
        launch_conv(bufC, w3a, bufA, m7, nullptr, mask13, thr, leak, 7, 128, 8, 8, 256, 4, 4, 3, 2, 1, 1);
        launch_conv(bufC, w3i, bufB, nullptr, nullptr, nullptr, thr, leak, 0, 128, 8, 8, 256, 4, 4, 1, 2, 0, 0);
        launch_conv(bufA, w3b, bufC, m8, bufB, nullptr, thr, leak, 8, 256, 4, 4, 256, 4, 4, 3, 1, 1, 1);
        // layer4 : inp = bufC
        launch_conv(bufC, w4a, bufA, m9, nullptr, mask15, thr, leak, 9, 256, 4, 4, 512, 2, 2, 3, 2, 1, 1);
        launch_conv(bufC, w4i, bufB, nullptr, nullptr, nullptr, thr, leak, 0, 256, 4, 4, 512, 2, 2, 1, 2, 0, 0);
        launch_conv(bufA, w4b, bufC, m10, bufB, nullptr, thr, leak, 10, 512, 2, 2, 512, 2, 2, 3, 1, 1, 1);
        // output accumulator
        fc_acc_kernel<<<320, 128>>>(bufC, w_fc, out);
    }
}

// round 3
// speedup vs baseline: 3.4947x; 3.4947x over previous
#include <cuda_runtime.h>

#define BATCH 32
#define KC 16
#define TIMESTEPS 8

// Membrane arena + activation ping-pong + split-K scratch.
__device__ float g_mem[8257536];
__device__ float g_bufA[2097152];
__device__ float g_bufB[2097152];
__device__ float g_bufC[2097152];
__device__ float g_scratch[524288];

struct ConvP {
    const float* __restrict__ in;
    const float* __restrict__ w;
    float*       out;
    float*       mem;
    const float* __restrict__ res;
    const float* __restrict__ mask;
    const float* __restrict__ thr;
    const float* __restrict__ leak;
    float*       scratch;
    int li;
    int Cin, Hin, Win;
    int Cout, Hout, Wout;
    int mode;      // 0 = raw store, 1 = fused LIF, 2 = split-K partial to scratch
    int Kper;      // K-range per split (multiple of KC)
    int N;         // BATCH*Hout*Wout
};

// ============================================================================
// Big-layer kernel: 64co x 128pos tile, 256 threads, 4x8 per-thread block,
// software-pipelined smem staging. Pos sub-tiles split as {tx*4, 64+tx*4}
// for conflict-free LDS.128.
// ============================================================================
template<int KH, int STRIDE, int PAD>
__global__ __launch_bounds__(256) void conv128(ConvP p) {
    __shared__ __align__(16) float As[KC][64];
    __shared__ __align__(16) float Bs[KC][128];

    const int tid = threadIdx.x;
    const int tx = tid & 15;
    const int ty = tid >> 4;
    const int pos0 = blockIdx.x * 128;
    const int co0  = blockIdx.y * 64;
    const int HW = p.Hout * p.Wout;
    const int KK = KH * KH;
    const int K  = p.Cin * KK;

    // A loader: lm = co-in-tile, k = lkq .. lkq+3
    const int lm  = tid >> 2;
    const int lkq = (tid & 3) * 4;
    const float* __restrict__ wrow = p.w + (size_t)(co0 + lm) * K;

    // B loader: lp = pos-in-tile, k = lbq .. lbq+7
    const int lp  = tid & 127;
    const int lbq = (tid >> 7) * 8;
    const int pp  = pos0 + lp;
    const int pb  = pp / HW;
    const int phw = pp - pb * HW;
    const int py  = phw / p.Wout;
    const int px  = phw - py * p.Wout;
    const int iy0 = py * STRIDE - PAD;
    const int ix0 = px * STRIDE - PAD;
    const float* __restrict__ inb = p.in + (size_t)pb * p.Cin * p.Hin * p.Win;

    float acc[4][8];
#pragma unroll
    for (int i = 0; i < 4; i++)
#pragma unroll
        for (int j = 0; j < 8; j++) acc[i][j] = 0.f;

    float ra[4], rb[8];

    auto loadA = [&](int k0) {
#pragma unroll
        for (int i = 0; i < 4; i++) {
            int kk = k0 + lkq + i;
            ra[i] = (kk < K) ? __ldg(wrow + kk) : 0.f;
        }
    };
    auto loadB = [&](int k0) {
#pragma unroll
        for (int i = 0; i < 8; i++) {
            int kk = k0 + lbq + i;
            float v = 0.f;
            if (kk < K) {
                int ci = kk / KK;                    // KK compile-time const
                int r  = kk - ci * KK;
                int ky = r / KH;
                int kx = r - ky * KH;
                int iy = iy0 + ky, ix = ix0 + kx;
                if (iy >= 0 && iy < p.Hin && ix >= 0 && ix < p.Win)
                    v = __ldg(inb + ((size_t)ci * p.Hin + iy) * p.Win + ix);
            }
            rb[i] = v;
        }
    };

    loadA(0); loadB(0);
    for (int k0 = 0; k0 < K; k0 += KC) {
#pragma unroll
        for (int i = 0; i < 4; i++) As[lkq + i][lm] = ra[i];
#pragma unroll
        for (int i = 0; i < 8; i++) Bs[lbq + i][lp] = rb[i];
        __syncthreads();
        if (k0 + KC < K) { loadA(k0 + KC); loadB(k0 + KC); }
#pragma unroll
        for (int k = 0; k < KC; k++) {
            const float4 a  = *(const float4*)&As[k][ty * 4];
            const float4 b0 = *(const float4*)&Bs[k][tx * 4];
            const float4 b1 = *(const float4*)&Bs[k][64 + tx * 4];
            const float av[4] = {a.x, a.y, a.z, a.w};
            const float bv[8] = {b0.x, b0.y, b0.z, b0.w, b1.x, b1.y, b1.z, b1.w};
#pragma unroll
            for (int i = 0; i < 4; i++)
#pragma unroll
                for (int j = 0; j < 8; j++)
                    acc[i][j] = fmaf(av[i], bv[j], acc[i][j]);
        }
        __syncthreads();
    }

    float th = 1.f, lkf = 1.f;
    if (p.mode == 1) { th = p.thr[p.li]; lkf = p.leak[p.li]; }

#pragma unroll
    for (int h = 0; h < 2; h++) {
        int posb = pos0 + h * 64 + tx * 4;   // 4 consecutive positions, same b
        int b  = posb / HW;
        int hw = posb - b * HW;
#pragma unroll
        for (int i = 0; i < 4; i++) {
            size_t g = ((size_t)b * p.Cout + co0 + ty * 4 + i) * HW + hw;
#pragma unroll
            for (int j = 0; j < 4; j++) {
                float d = acc[i][h * 4 + j];
                size_t gi = g + j;
                if (p.mode == 0) {
                    p.out[gi] = d;
                } else {
                    if (p.res) d += p.res[gi];
                    float m  = lkf * p.mem[gi] + d;
                    float mt = m / th - 1.f;
                    float s  = (mt > 0.f) ? 1.f : 0.f;
                    p.mem[gi] = m - th * s;
                    float o = s;
                    if (p.mask) o *= p.mask[gi];
                    p.out[gi] = o;
                }
            }
        }
    }
}

// ============================================================================
// Small/deep-layer kernel: 64co x 32pos tile, 128 threads, 4x4 per-thread,
// split-K over blockIdx.z (partials to scratch when mode==2).
// ============================================================================
template<int KH, int STRIDE, int PAD>
__global__ __launch_bounds__(128) void conv_split(ConvP p) {
    __shared__ __align__(16) float As[KC][64];
    __shared__ __align__(16) float Bs[KC][32];

    const int tid = threadIdx.x;
    const int tx = tid & 7;
    const int ty = tid >> 3;
    const int pos0 = blockIdx.x * 32;
    const int co0  = blockIdx.y * 64;
    const int HW = p.Hout * p.Wout;
    const int KK = KH * KH;
    const int K  = p.Cin * KK;
    const int kstart = blockIdx.z * p.Kper;
    const int kend   = (kstart + p.Kper < K) ? kstart + p.Kper : K;

    const int lm  = tid >> 1;
    const int lkq = (tid & 1) * 8;
    const float* __restrict__ wrow = p.w + (size_t)(co0 + lm) * K;

    const int lp  = tid & 31;
    const int lbq = (tid >> 5) * 4;
    const int pp  = pos0 + lp;
    const int pb  = pp / HW;
    const int phw = pp - pb * HW;
    const int py  = phw / p.Wout;
    const int px  = phw - py * p.Wout;
    const int iy0 = py * STRIDE - PAD;
    const int ix0 = px * STRIDE - PAD;
    const float* __restrict__ inb = p.in + (size_t)pb * p.Cin * p.Hin * p.Win;

    float acc[4][4];
#pragma unroll
    for (int i = 0; i < 4; i++)
#pragma unroll
        for (int j = 0; j < 4; j++) acc[i][j] = 0.f;

    float ra[8], rb[4];

    auto loadA = [&](int k0) {
#pragma unroll
        for (int i = 0; i < 8; i++) {
            int kk = k0 + lkq + i;
            ra[i] = (kk < kend) ? __ldg(wrow + kk) : 0.f;
        }
    };
    auto loadB = [&](int k0) {
#pragma unroll
        for (int i = 0; i < 4; i++) {
            int kk = k0 + lbq + i;
            float v = 0.f;
            if (kk < kend) {
                int ci = kk / KK;
                int r  = kk - ci * KK;
                int ky = r / KH;
                int kx = r - ky * KH;
                int iy = iy0 + ky, ix = ix0 + kx;
                if (iy >= 0 && iy < p.Hin && ix >= 0 && ix < p.Win)
                    v = __ldg(inb + ((size_t)ci * p.Hin + iy) * p.Win + ix);
            }
            rb[i] = v;
        }
    };

    loadA(kstart); loadB(kstart);
    for (int k0 = kstart; k0 < kend; k0 += KC) {
#pragma unroll
        for (int i = 0; i < 8; i++) As[lkq + i][lm] = ra[i];
#pragma unroll
        for (int i = 0; i < 4; i++) Bs[lbq + i][lp] = rb[i];
        __syncthreads();
        if (k0 + KC < kend) { loadA(k0 + KC); loadB(k0 + KC); }
#pragma unroll
        for (int k = 0; k < KC; k++) {
            const float4 a  = *(const float4*)&As[k][ty * 4];
            const float4 b0 = *(const float4*)&Bs[k][tx * 4];
            const float av[4] = {a.x, a.y, a.z, a.w};
            const float bv[4] = {b0.x, b0.y, b0.z, b0.w};
#pragma unroll
            for (int i = 0; i < 4; i++)
#pragma unroll
                for (int j = 0; j < 4; j++)
                    acc[i][j] = fmaf(av[i], bv[j], acc[i][j]);
        }
        __syncthreads();
    }

    int posb = pos0 + tx * 4;     // 4 consecutive positions, same b (HW >= 4)
    int b  = posb / HW;
    int hw = posb - b * HW;

    if (p.mode == 2) {
#pragma unroll
        for (int i = 0; i < 4; i++) {
            size_t s = ((size_t)blockIdx.z * p.Cout + co0 + ty * 4 + i) * p.N + posb;
#pragma unroll
            for (int j = 0; j < 4; j++) p.scratch[s + j] = acc[i][j];
        }
        return;
    }

    float th = 1.f, lkf = 1.f;
    if (p.mode == 1) { th = p.thr[p.li]; lkf = p.leak[p.li]; }
#pragma unroll
    for (int i = 0; i < 4; i++) {
        size_t g = ((size_t)b * p.Cout + co0 + ty * 4 + i) * HW + hw;
#pragma unroll
        for (int j = 0; j < 4; j++) {
            float d = acc[i][j];
            size_t gi = g + j;
            if (p.mode == 0) {
                p.out[gi] = d;
            } else {
                if (p.res) d += p.res[gi];
                float m  = lkf * p.mem[gi] + d;
                float mt = m / th - 1.f;
                float s  = (mt > 0.f) ? 1.f : 0.f;
                p.mem[gi] = m - th * s;
                float o = s;
                if (p.mask) o *= p.mask[gi];
                p.out[gi] = o;
            }
        }
    }
}

// Combine split-K partials + residual + LIF.
__global__ void combine_lif(const float* __restrict__ scratch, int S, int Cout,
                            int N, int HW,
                            const float* __restrict__ res,
                            const float* __restrict__ mask,
                            float* mem, float* out,
                            const float* __restrict__ thr,
                            const float* __restrict__ leak, int li) {
    int idx = blockIdx.x * blockDim.x + threadIdx.x;
    int total = Cout * N;
    if (idx >= total) return;
    int co  = idx / N;
    int pos = idx - co * N;
    float d = 0.f;
    for (int s = 0; s < S; s++)
        d += scratch[((size_t)s * Cout + co) * N + pos];
    int b = pos / HW, hw = pos - b * HW;
    size_t g = ((size_t)b * Cout + co) * HW + hw;
    if (res) d += res[g];
    float th = thr[li], lkf = leak[li];
    float m  = lkf * mem[g] + d;
    float mt = m / th - 1.f;
    float s_ = (mt > 0.f) ? 1.f : 0.f;
    mem[g] = m - th * s_;
    float o = s_;
    if (mask) o *= mask[g];
    out[g] = o;
}

__global__ void zero_kernel(float* mem, int n, float* out, int nout) {
    int i = blockIdx.x * blockDim.x + threadIdx.x;
    if (i < n) mem[i] = 0.f;
    if (i < nout) out[i] = 0.f;
}

__global__ void avgpool2_kernel(const float* __restrict__ in, float* out,
                                int C, int H, int W) {
    int Ho = H >> 1, Wo = W >> 1;
    int total = BATCH * C * Ho * Wo;
    int idx = blockIdx.x * blockDim.x + threadIdx.x;
    if (idx >= total) return;
    int x = idx % Wo; int t = idx / Wo;
    int y = t % Ho;   t /= Ho;
    int c = t % C;    int b = t / C;
    const float* pp = in + (((size_t)b * C + c) * H + y * 2) * W + x * 2;
    out[idx] = 0.25f * (pp[0] + pp[1] + pp[W] + pp[W + 1]);
}

__global__ void fc_acc_kernel(const float* __restrict__ o,
                              const float* __restrict__ wfc, float* out) {
    int bk = blockIdx.x;
    int b = bk / 10, k = bk % 10;
    const float* op = o + (size_t)b * 2048;
    const float* wp = wfc + (size_t)k * 2048;
    float s = 0.f;
    for (int j = threadIdx.x; j < 2048; j += 128) s += op[j] * wp[j];
    __shared__ float red[128];
    red[threadIdx.x] = s;
    __syncthreads();
    for (int st = 64; st > 0; st >>= 1) {
        if (threadIdx.x < st) red[threadIdx.x] += red[threadIdx.x + st];
        __syncthreads();
    }
    if (threadIdx.x == 0) out[b * 10 + k] += red[0];
}

// ============================================================================
// Host side
// ============================================================================

static ConvP mkp(const float* in, const float* w, float* out, float* mem,
                 const float* res, const float* mask,
                 const float* thr, const float* leak, float* scratch, int li,
                 int Cin, int Hin, int Win, int Cout, int Hout, int Wout,
                 int mode, int Kper) {
    ConvP p;
    p.in = in; p.w = w; p.out = out; p.mem = mem; p.res = res; p.mask = mask;
    p.thr = thr; p.leak = leak; p.scratch = scratch; p.li = li;
    p.Cin = Cin; p.Hin = Hin; p.Win = Win;
    p.Cout = Cout; p.Hout = Hout; p.Wout = Wout;
    p.mode = mode; p.Kper = Kper; p.N = BATCH * Hout * Wout;
    return p;
}

extern "C" void kernel_launch(void* const* d_in, const int* in_sizes, int n_in,
                              void* d_out, int out_size) {
    const float* x      = (const float*)d_in[0];
    const float* w_pre0 = (const float*)d_in[1];
    const float* w_pre1 = (const float*)d_in[2];
    const float* w_pre2 = (const float*)d_in[3];
    const float* w1a    = (const float*)d_in[4];
    const float* w1b    = (const float*)d_in[5];
    const float* w2a    = (const float*)d_in[6];
    const float* w2b    = (const float*)d_in[7];
    const float* w2i    = (const float*)d_in[8];
    const float* w3a    = (const float*)d_in[9];
    const float* w3b    = (const float*)d_in[10];
    const float* w3i    = (const float*)d_in[11];
    const float* w4a    = (const float*)d_in[12];
    const float* w4b    = (const float*)d_in[13];
    const float* w4i    = (const float*)d_in[14];
    const float* w_fc   = (const float*)d_in[15];
    const float* thr    = (const float*)d_in[16];
    const float* leak   = (const float*)d_in[17];
    const float* mask2  = (const float*)d_in[18];
    const float* mask5  = (const float*)d_in[19];
    const float* mask9  = (const float*)d_in[20];
    const float* mask11 = (const float*)d_in[21];
    const float* mask13 = (const float*)d_in[22];
    const float* mask15 = (const float*)d_in[23];

    float *memBase, *bufA, *bufB, *bufC, *scr;
    cudaGetSymbolAddress((void**)&memBase, g_mem);
    cudaGetSymbolAddress((void**)&bufA, g_bufA);
    cudaGetSymbolAddress((void**)&bufB, g_bufB);
    cudaGetSymbolAddress((void**)&bufC, g_bufC);
    cudaGetSymbolAddress((void**)&scr, g_scratch);
    float* out = (float*)d_out;

    float* m0  = memBase + 0;
    float* m1  = memBase + 2097152;
    float* m2  = memBase + 4194304;
    float* m3  = memBase + 6291456;
    float* m4  = memBase + 6815744;
    float* m5  = memBase + 7340032;
    float* m6  = memBase + 7602176;
    float* m7  = memBase + 7864320;
    float* m8  = memBase + 7995392;
    float* m9  = memBase + 8126464;
    float* m10 = memBase + 8192000;

    zero_kernel<<<(8257536 + 255) / 256, 256>>>(memBase, 8257536, out, 320);

    for (int t = 0; t < TIMESTEPS; t++) {
        ConvP p;
        // ---- pre_process: three 3x3 convs @32x32, Cout=64 ----
        p = mkp(x, w_pre0, bufA, m0, nullptr, mask2, thr, leak, scr, 0,
                3, 32, 32, 64, 32, 32, 1, 0);
        conv128<3,1,1><<<dim3(32768/128, 1), 256>>>(p);
        p = mkp(bufA, w_pre1, bufB, m1, nullptr, mask5, thr, leak, scr, 1,
                64, 32, 32, 64, 32, 32, 1, 0);
        conv128<3,1,1><<<dim3(32768/128, 1), 256>>>(p);
        p = mkp(bufB, w_pre2, bufA, m2, nullptr, nullptr, thr, leak, scr, 2,
                64, 32, 32, 64, 32, 32, 1, 0);
        conv128<3,1,1><<<dim3(32768/128, 1), 256>>>(p);
        avgpool2_kernel<<<(BATCH*64*16*16 + 255)/256, 256>>>(bufA, bufB, 64, 32, 32);

        // ---- layer1 (identity shortcut), inp = bufB, 16x16, Cout=64 ----
        p = mkp(bufB, w1a, bufA, m3, nullptr, mask9, thr, leak, scr, 3,
                64, 16, 16, 64, 16, 16, 1, 576);
        conv_split<3,1,1><<<dim3(8192/32, 1, 1), 128>>>(p);
        p = mkp(bufA, w1b, bufC, m4, bufB, nullptr, thr, leak, scr, 4,
                64, 16, 16, 64, 16, 16, 1, 576);
        conv_split<3,1,1><<<dim3(8192/32, 1, 1), 128>>>(p);

        // ---- layer2, inp = bufC, out 8x8, Cout=128 ----
        p = mkp(bufC, w2a, bufA, m5, nullptr, mask11, thr, leak, scr, 5,
                64, 16, 16, 128, 8, 8, 1, 576);
        conv_split<3,2,1><<<dim3(2048/32, 2, 1), 128>>>(p);
        p = mkp(bufC, w2i, bufB, nullptr, nullptr, nullptr, thr, leak, scr, 0,
                64, 16, 16, 128, 8, 8, 0, 64);
        conv_split<1,2,0><<<dim3(2048/32, 2, 1), 128>>>(p);
        p = mkp(bufA, w2b, nullptr, nullptr, nullptr, nullptr, thr, leak, scr, 0,
                128, 8, 8, 128, 8, 8, 2, 576);          // K=1152, S=2
        conv_split<3,1,1><<<dim3(2048/32, 2, 2), 128>>>(p);
        combine_lif<<<(128*2048 + 255)/256, 256>>>(scr, 2, 128, 2048, 64,
                bufB, nullptr, m6, bufC, thr, leak, 6);

        // ---- layer3, inp = bufC, out 4x4, Cout=256 ----
        p = mkp(bufC, w3a, nullptr, nullptr, nullptr, nullptr, thr, leak, scr, 0,
                128, 8, 8, 256, 4, 4, 2, 576);          // K=1152, S=2
        conv_split<3,2,1><<<dim3(512/32, 4, 2), 128>>>(p);
        combine_lif<<<(256*512 + 255)/256, 256>>>(scr, 2, 256, 512, 16,
                nullptr, mask13, m7, bufA, thr, leak, 7);
        p = mkp(bufC, w3i, bufB, nullptr, nullptr, nullptr, thr, leak, scr, 0,
                128, 8, 8, 256, 4, 4, 0, 128);
        conv_split<1,2,0><<<dim3(512/32, 4, 1), 128>>>(p);
        p = mkp(bufA, w3b, nullptr, nullptr, nullptr, nullptr, thr, leak, scr, 0,
                256, 4, 4, 256, 4, 4, 2, 576);          // K=2304, S=4
        conv_split<3,1,1><<<dim3(512/32, 4, 4), 128>>>(p);
        combine_lif<<<(256*512 + 255)/256, 256>>>(scr, 4, 256, 512, 16,
                bufB, nullptr, m8, bufC, thr, leak, 8);

        // ---- layer4, inp = bufC, out 2x2, Cout=512 ----
        p = mkp(bufC, w4a, nullptr, nullptr, nullptr, nullptr, thr, leak, scr, 0,
                256, 4, 4, 512, 2, 2, 2, 576);          // K=2304, S=4
        conv_split<3,2,1><<<dim3(128/32, 8, 4), 128>>>(p);
        combine_lif<<<(512*128 + 255)/256, 256>>>(scr, 4, 512, 128, 4,
                nullptr, mask15, m9, bufA, thr, leak, 9);
        p = mkp(bufC, w4i, bufB, nullptr, nullptr, nullptr, thr, leak, scr, 0,
                256, 4, 4, 512, 2, 2, 0, 256);
        conv_split<1,2,0><<<dim3(128/32, 8, 1), 128>>>(p);
        p = mkp(bufA, w4b, nullptr, nullptr, nullptr, nullptr, thr, leak, scr, 0,
                512, 2, 2, 512, 2, 2, 2, 576);          // K=4608, S=8
        conv_split<3,1,1><<<dim3(128/32, 8, 8), 128>>>(p);
        combine_lif<<<(512*128 + 255)/256, 256>>>(scr, 8, 512, 128, 4,
                bufB, nullptr, m10, bufC, thr, leak, 10);

        // ---- output accumulator ----
        fc_acc_kernel<<<320, 128>>>(bufC, w_fc, out);
    }
}